// round 7
// baseline (speedup 1.0000x reference)
#include <cuda_runtime.h>
#include <cstdint>

#define N_PTS   400000
#define NTILE1  1563                 // pf1 blocks of 256
#define NPT     (NTILE1 * 256)       // 400128 padded points
#define NXY     468
#define CANVAS  (468 * 468)          // 219024
#define VXY     0.32f
#define VZf     6.0f
#define PCMINX  (-74.88f)
#define PCMINY  (-74.88f)
#define PCMINZ  (-2.0f)

// -------- scratch (static device globals; no allocations allowed) ----------
__device__ int   g_flat[NPT];                 // padded; tail zeroed
__device__ int   g_cnt[CANVAS];
__device__ float g_vsum[CANVAS * 3];
__device__ float g_v1[CANVAS * 64];           // 56 MB
__device__ float g_bias[CANVAS * 64];         // 56 MB  (= v1 @ W2[64:])
__device__ float g_pf1T[64 * NPT];            // 102 MB, transposed [k][pt]

// packed f32x2 FMA (Blackwell FFMA2) — d = a*b + d on 2 packed fp32
__device__ __forceinline__ void fma2(uint64_t& d, uint64_t a, uint64_t b) {
    asm("fma.rn.f32x2 %0, %1, %2, %0;" : "+l"(d) : "l"(a), "l"(b));
}

// ---------------------------------------------------------------------------
// K0: zero cnt / vsum / v1 / out / g_flat tail
// ---------------------------------------------------------------------------
__global__ void k_init(float* __restrict__ out) {
    int idx = blockIdx.x * blockDim.x + threadIdx.x;
    int stride = gridDim.x * blockDim.x;
    const int n4 = (CANVAS * 64) / 4;
    float4 z = make_float4(0.f, 0.f, 0.f, 0.f);
    float4* o4 = (float4*)out;
    float4* v4 = (float4*)g_v1;
    for (int i = idx; i < n4; i += stride) {
        o4[i] = z;
        v4[i] = z;
    }
    for (int i = idx; i < CANVAS; i += stride) {
        g_cnt[i] = 0;
        g_vsum[3 * i + 0] = 0.f;
        g_vsum[3 * i + 1] = 0.f;
        g_vsum[3 * i + 2] = 0.f;
    }
    for (int i = N_PTS + idx; i < NPT; i += stride) g_flat[i] = 0;
}

// ---------------------------------------------------------------------------
// K1: per-point voxel index + count / xyz-sum scatter
// ---------------------------------------------------------------------------
__device__ __forceinline__ int voxel_coord(float v, float vmin, float vox, int nmax) {
    int c = (int)floorf(__fdiv_rn(v - vmin, vox));
    return min(max(c, 0), nmax - 1);
}

__global__ void k_scatter(const float* __restrict__ pts) {
    int i = blockIdx.x * blockDim.x + threadIdx.x;
    if (i >= N_PTS) return;
    float x = pts[i * 5 + 0];
    float y = pts[i * 5 + 1];
    float z = pts[i * 5 + 2];
    int cx = voxel_coord(x, PCMINX, VXY, NXY);
    int cy = voxel_coord(y, PCMINY, VXY, NXY);
    int flat = cy * NXY + cx;          // NZ==1 -> cz always 0
    g_flat[i] = flat;
    atomicAdd(&g_cnt[flat], 1);
    atomicAdd(&g_vsum[3 * flat + 0], x);
    atomicAdd(&g_vsum[3 * flat + 1], y);
    atomicAdd(&g_vsum[3 * flat + 2], z);
}

// ---------------------------------------------------------------------------
// K2: thread-per-point pf1 = relu(features @ W1).
// atomicMax into v1 (relu >= 0, v1 zero-init -> exact); outputs transposed in
// smem, written coalesced to g_pf1T[k][pt].
// ---------------------------------------------------------------------------
__global__ __launch_bounds__(256) void k_pf1(const float* __restrict__ pts,
                                             const float* __restrict__ W1) {
    __shared__ float sW1[11 * 64];
    __shared__ float sT[64 * 256];
    int tid = threadIdx.x;
    for (int i = tid; i < 11 * 64; i += 256) sW1[i] = W1[i];
    __syncthreads();

    int gp = blockIdx.x * 256 + tid;
    bool valid = (gp < N_PTS);

    float f[11];
    #pragma unroll
    for (int k = 0; k < 11; k++) f[k] = 0.f;
    int flat = 0;

    if (valid) {
        float x  = pts[gp * 5 + 0];
        float y  = pts[gp * 5 + 1];
        float z  = pts[gp * 5 + 2];
        float p3 = pts[gp * 5 + 3];
        float p4 = pts[gp * 5 + 4];
        flat = g_flat[gp];
        float inv = 1.0f / fmaxf((float)g_cnt[flat], 1.0f);
        float mx = g_vsum[3 * flat + 0] * inv;
        float my = g_vsum[3 * flat + 1] * inv;
        float mz = g_vsum[3 * flat + 2] * inv;
        int cxv = flat % NXY;
        int cyv = flat / NXY;
        f[0] = x;  f[1] = y;  f[2] = z;  f[3] = p3;  f[4] = p4;
        f[5] = x - mx;  f[6] = y - my;  f[7] = z - mz;
        f[8]  = x - ((float)cxv * VXY + (VXY * 0.5f + PCMINX));
        f[9]  = y - ((float)cyv * VXY + (VXY * 0.5f + PCMINY));
        f[10] = z - (VZf * 0.5f + PCMINZ);
    }

    const float4* w4 = (const float4*)sW1;   // [11][16] float4
    #pragma unroll 4
    for (int cg = 0; cg < 16; cg++) {
        float a0 = 0.f, a1 = 0.f, a2 = 0.f, a3 = 0.f;
        #pragma unroll
        for (int k = 0; k < 11; k++) {
            float4 w = w4[k * 16 + cg];
            a0 = fmaf(f[k], w.x, a0);
            a1 = fmaf(f[k], w.y, a1);
            a2 = fmaf(f[k], w.z, a2);
            a3 = fmaf(f[k], w.w, a3);
        }
        a0 = fmaxf(a0, 0.f); a1 = fmaxf(a1, 0.f);
        a2 = fmaxf(a2, 0.f); a3 = fmaxf(a3, 0.f);
        int c = cg * 4;
        sT[(c + 0) * 256 + tid] = a0;
        sT[(c + 1) * 256 + tid] = a1;
        sT[(c + 2) * 256 + tid] = a2;
        sT[(c + 3) * 256 + tid] = a3;
        if (valid) {
            int* vb = (int*)&g_v1[(size_t)flat * 64 + c];
            if (a0 > 0.f) atomicMax(vb + 0, __float_as_int(a0));
            if (a1 > 0.f) atomicMax(vb + 1, __float_as_int(a1));
            if (a2 > 0.f) atomicMax(vb + 2, __float_as_int(a2));
            if (a3 > 0.f) atomicMax(vb + 3, __float_as_int(a3));
        }
    }
    __syncthreads();

    // coalesced transposed write: g_pf1T[k][b0 + pt]
    int b0 = blockIdx.x * 256;
    const float4* src = (const float4*)sT;
    #pragma unroll 4
    for (int i = tid; i < 64 * 64; i += 256) {
        int k = i >> 6, q = i & 63;
        *(float4*)(g_pf1T + (size_t)k * NPT + b0 + q * 4) = src[i];
    }
}

// ===========================================================================
// Shared GEMM microkernel pieces (4 pts x 8 cols per thread, f32x2 pairs)
// sA: [64 k][SA_S] k-major, SA_S=132.  sB: dup'd interleaved [64][128].
// ===========================================================================
#define SA_S      132
#define SA_WORDS  (64 * SA_S)              // 8448
#define SB_WORDS  (64 * 128)               // 8192
#define SMEM_GEMM ((SA_WORDS + SB_WORDS) * 4)   // 66560 bytes

// stage one 64-row chunk of W2 duplicated+interleaved: col c of k-row k at
// word off = k*128 + ((c&7)>>1)*32 + (c>>3)*4 + (c&1)*2, value {w,w}
__device__ __forceinline__ void stage_B(float* sB, const float* W2chunk, int tid) {
    for (int i = tid; i < 4096; i += 256) {
        int k = i >> 6, c = i & 63;
        float wv = W2chunk[k * 64 + c];
        int off = k * 128 + (((c & 7) >> 1) << 5) + ((c >> 3) << 2) + ((c & 1) << 1);
        *(float2*)&sB[off] = make_float2(wv, wv);
    }
}

// mainloop: 64 rank-1 updates into acc[2][8] (2 point-pairs x 8 cols)
__device__ __forceinline__ void gemm_main(const float* sA, const float* sB,
                                          int ty, int cx, uint64_t acc[2][8]) {
    #pragma unroll 4
    for (int k = 0; k < 64; k++) {
        const float* a = sA + k * SA_S + ty * 4;
        ulonglong2 A = *(const ulonglong2*)a;          // pairs (p0,p1),(p2,p3)
        const float* b = sB + k * 128 + cx * 4;
        ulonglong2 B0 = *(const ulonglong2*)(b + 0);   // cols 8cx+0,1 dup
        ulonglong2 B1 = *(const ulonglong2*)(b + 32);  // cols 8cx+2,3
        ulonglong2 B2 = *(const ulonglong2*)(b + 64);  // cols 8cx+4,5
        ulonglong2 B3 = *(const ulonglong2*)(b + 96);  // cols 8cx+6,7
        uint64_t Bv[8] = {B0.x, B0.y, B1.x, B1.y, B2.x, B2.y, B3.x, B3.y};
        #pragma unroll
        for (int c = 0; c < 8; c++) {
            fma2(acc[0][c], A.x, Bv[c]);
            fma2(acc[1][c], A.y, Bv[c]);
        }
    }
}

// ---------------------------------------------------------------------------
// K3: bias[v] = v1[v] @ W2[64:128]  (per-voxel, no relu, no atomics)
// tile: 128 voxels x 64 cols, 256 threads
// ---------------------------------------------------------------------------
__global__ __launch_bounds__(256, 3)
void k_bias(const float* __restrict__ W2, int unused) {
    extern __shared__ float smem[];
    float* sA = smem;
    float* sB = smem + SA_WORDS;

    int tid = threadIdx.x;
    int v0  = blockIdx.x * 128;
    int ty  = tid >> 3;
    int cx  = tid & 7;

    stage_B(sB, W2 + 64 * 64, tid);

    // stage A = v1 rows v0..v0+127, k-major transpose (conflict-free bit trick)
    const float4* v1_4 = (const float4*)g_v1;
    for (int i = tid; i < 2048; i += 256) {
        int pt = (i & 15) | ((i >> 8) << 4);
        int q  = (i >> 4) & 15;
        int vv = v0 + pt;
        float4 v = (vv < CANVAS) ? v1_4[(size_t)vv * 16 + q]
                                 : make_float4(0.f, 0.f, 0.f, 0.f);
        int kb = q * 4;
        sA[(kb + 0) * SA_S + pt] = v.x;
        sA[(kb + 1) * SA_S + pt] = v.y;
        sA[(kb + 2) * SA_S + pt] = v.z;
        sA[(kb + 3) * SA_S + pt] = v.w;
    }
    __syncthreads();

    uint64_t acc[2][8];
    #pragma unroll
    for (int p = 0; p < 2; p++)
        #pragma unroll
        for (int c = 0; c < 8; c++) acc[p][c] = 0ull;

    gemm_main(sA, sB, ty, cx, acc);

    // store bias rows (coalesced-ish float4 x2 per point)
    #pragma unroll
    for (int pr = 0; pr < 2; pr++) {
        #pragma unroll
        for (int half = 0; half < 2; half++) {
            int vox = v0 + ty * 4 + pr * 2 + half;
            if (vox >= CANVAS) continue;
            float s[8];
            #pragma unroll
            for (int c = 0; c < 8; c++) {
                uint32_t bits = half ? (uint32_t)(acc[pr][c] >> 32)
                                     : (uint32_t)(acc[pr][c] & 0xffffffffu);
                s[c] = __uint_as_float(bits);
            }
            float4* o = (float4*)(g_bias + (size_t)vox * 64 + cx * 8);
            o[0] = make_float4(s[0], s[1], s[2], s[3]);
            o[1] = make_float4(s[4], s[5], s[6], s[7]);
        }
    }
}

// ---------------------------------------------------------------------------
// K4: pf2 = relu(pf1 @ W2[:64] + bias[flat]), scatter-max into out.
// tile: 128 points x 64 cols, 256 threads.  A read from transposed g_pf1T.
// ---------------------------------------------------------------------------
__global__ __launch_bounds__(256, 3)
void k_pf2(const float* __restrict__ W2, float* __restrict__ out) {
    extern __shared__ float smem[];
    float* sA = smem;
    float* sB = smem + SA_WORDS;

    int tid = threadIdx.x;
    int p0  = blockIdx.x * 128;        // 3125 * 128 = 400000 exactly
    int ty  = tid >> 3;
    int cx  = tid & 7;

    stage_B(sB, W2, tid);

    // stage A: coalesced copy from transposed pf1
    for (int i = tid; i < 2048; i += 256) {
        int k = i >> 5, q = i & 31;
        float4 v = *(const float4*)(g_pf1T + (size_t)k * NPT + p0 + q * 4);
        *(float4*)&sA[k * SA_S + q * 4] = v;
    }
    __syncthreads();

    uint64_t acc[2][8];
    #pragma unroll
    for (int p = 0; p < 2; p++)
        #pragma unroll
        for (int c = 0; c < 8; c++) acc[p][c] = 0ull;

    gemm_main(sA, sB, ty, cx, acc);

    // epilogue: + bias[flat], relu, guarded scatter atomicMax
    #pragma unroll
    for (int pr = 0; pr < 2; pr++) {
        #pragma unroll
        for (int half = 0; half < 2; half++) {
            int gp = p0 + ty * 4 + pr * 2 + half;
            int fl = g_flat[gp];
            const float4* bb = (const float4*)(g_bias + (size_t)fl * 64 + cx * 8);
            float4 blo = bb[0];
            float4 bhi = bb[1];
            float bias[8] = {blo.x, blo.y, blo.z, blo.w,
                             bhi.x, bhi.y, bhi.z, bhi.w};
            int* o = (int*)(out + (size_t)fl * 64 + cx * 8);
            #pragma unroll
            for (int c = 0; c < 8; c++) {
                uint32_t bits = half ? (uint32_t)(acc[pr][c] >> 32)
                                     : (uint32_t)(acc[pr][c] & 0xffffffffu);
                float v = __uint_as_float(bits) + bias[c];
                if (v > 0.f) atomicMax(o + c, __float_as_int(v));
            }
        }
    }
}

// ---------------------------------------------------------------------------
extern "C" void kernel_launch(void* const* d_in, const int* in_sizes, int n_in,
                              void* d_out, int out_size) {
    const float* points = (const float*)d_in[0];  // [400000, 5]
    const float* W1     = (const float*)d_in[1];  // [11, 64]
    const float* W2     = (const float*)d_in[2];  // [128, 64]
    float* out = (float*)d_out;                   // [219024, 64]

    cudaFuncSetAttribute(k_bias, cudaFuncAttributeMaxDynamicSharedMemorySize,
                         SMEM_GEMM);
    cudaFuncSetAttribute(k_pf2, cudaFuncAttributeMaxDynamicSharedMemorySize,
                         SMEM_GEMM);

    k_init<<<8192, 256>>>(out);
    k_scatter<<<(N_PTS + 255) / 256, 256>>>(points);
    k_pf1<<<NTILE1, 256>>>(points, W1);
    k_bias<<<(CANVAS + 127) / 128, 256, SMEM_GEMM>>>(W2, 0);
    k_pf2<<<N_PTS / 128, 256, SMEM_GEMM>>>(W2, out);
}

// round 8
// speedup vs baseline: 1.0752x; 1.0752x over previous
#include <cuda_runtime.h>
#include <cstdint>

#define N_PTS   400000
#define NXY     468
#define CANVAS  (468 * 468)          // 219024
#define VXY     0.32f
#define VZf     6.0f
#define PCMINX  (-74.88f)
#define PCMINY  (-74.88f)
#define PCMINZ  (-2.0f)

// -------- scratch (static device globals; no allocations allowed) ----------
__device__ int   g_flat[N_PTS];
__device__ int   g_cnt[CANVAS];
__device__ float g_vsum[CANVAS * 3];
__device__ float g_v1[CANVAS * 64];     // 56 MB
__device__ float g_pf1[(size_t)N_PTS * 64];     // 102 MB row-major [pt][64]

// ---------------------------------------------------------------------------
// K0: zero cnt / vsum / v1 / out
// ---------------------------------------------------------------------------
__global__ void k_init(float* __restrict__ out) {
    int idx = blockIdx.x * blockDim.x + threadIdx.x;
    int stride = gridDim.x * blockDim.x;
    const int n4 = (CANVAS * 64) / 4;
    float4 z = make_float4(0.f, 0.f, 0.f, 0.f);
    float4* o4 = (float4*)out;
    float4* v4 = (float4*)g_v1;
    for (int i = idx; i < n4; i += stride) {
        o4[i] = z;
        v4[i] = z;
    }
    for (int i = idx; i < CANVAS; i += stride) {
        g_cnt[i] = 0;
        g_vsum[3 * i + 0] = 0.f;
        g_vsum[3 * i + 1] = 0.f;
        g_vsum[3 * i + 2] = 0.f;
    }
}

// ---------------------------------------------------------------------------
// K1: per-point voxel index + count / xyz-sum scatter
// ---------------------------------------------------------------------------
__device__ __forceinline__ int voxel_coord(float v, float vmin, float vox, int nmax) {
    int c = (int)floorf(__fdiv_rn(v - vmin, vox));
    return min(max(c, 0), nmax - 1);
}

__global__ void k_scatter(const float* __restrict__ pts) {
    int i = blockIdx.x * blockDim.x + threadIdx.x;
    if (i >= N_PTS) return;
    float x = pts[i * 5 + 0];
    float y = pts[i * 5 + 1];
    float z = pts[i * 5 + 2];
    int cx = voxel_coord(x, PCMINX, VXY, NXY);
    int cy = voxel_coord(y, PCMINY, VXY, NXY);
    int flat = cy * NXY + cx;          // NZ==1 -> cz always 0
    g_flat[i] = flat;
    atomicAdd(&g_cnt[flat], 1);
    atomicAdd(&g_vsum[3 * flat + 0], x);
    atomicAdd(&g_vsum[3 * flat + 1], y);
    atomicAdd(&g_vsum[3 * flat + 2], z);
}

// ---------------------------------------------------------------------------
// K2: pf1 = relu(features @ W1); store g_pf1 row-major, atomicMax into v1.
// warp per point; lane -> channels (lane, lane+32).  (R1-proven shape.)
// ---------------------------------------------------------------------------
__global__ void k_pf1(const float* __restrict__ pts, const float* __restrict__ W1) {
    __shared__ float sW1[11 * 64];
    int tid = threadIdx.x;
    for (int i = tid; i < 11 * 64; i += 256) sW1[i] = W1[i];
    __syncthreads();

    int warp = tid >> 5;
    int lane = tid & 31;
    int i = blockIdx.x * 8 + warp;
    if (i >= N_PTS) return;

    float x  = pts[i * 5 + 0];
    float y  = pts[i * 5 + 1];
    float z  = pts[i * 5 + 2];
    float p3 = pts[i * 5 + 3];
    float p4 = pts[i * 5 + 4];

    int flat = g_flat[i];
    float inv = 1.0f / fmaxf((float)g_cnt[flat], 1.0f);
    float mx = g_vsum[3 * flat + 0] * inv;
    float my = g_vsum[3 * flat + 1] * inv;
    float mz = g_vsum[3 * flat + 2] * inv;

    int cxv = flat % NXY;
    int cyv = flat / NXY;

    float f[11];
    f[0] = x;  f[1] = y;  f[2] = z;  f[3] = p3;  f[4] = p4;
    f[5] = x - mx;  f[6] = y - my;  f[7] = z - mz;
    f[8]  = x - ((float)cxv * VXY + (VXY * 0.5f + PCMINX));
    f[9]  = y - ((float)cyv * VXY + (VXY * 0.5f + PCMINY));
    f[10] = z - (VZf * 0.5f + PCMINZ);

    float a0 = 0.f, a1 = 0.f;
    #pragma unroll
    for (int k = 0; k < 11; k++) {
        a0 = fmaf(f[k], sW1[k * 64 + lane], a0);
        a1 = fmaf(f[k], sW1[k * 64 + lane + 32], a1);
    }
    a0 = fmaxf(a0, 0.f);
    a1 = fmaxf(a1, 0.f);

    g_pf1[(size_t)i * 64 + lane]      = a0;
    g_pf1[(size_t)i * 64 + lane + 32] = a1;

    // relu >= 0 and v1 zero-initialized -> int atomicMax reproduces
    // where(occ, segment_max, 0) exactly.
    if (a0 > 0.f) atomicMax((int*)&g_v1[(size_t)flat * 64 + lane],      __float_as_int(a0));
    if (a1 > 0.f) atomicMax((int*)&g_v1[(size_t)flat * 64 + lane + 32], __float_as_int(a1));
}

// ---------------------------------------------------------------------------
// K3: pf2 = relu([pf1, v1[flat]] @ W2), scatter-max into out.
// OCCUPANCY-FIRST SHAPE: tile 64 pts x 64 cols, 256 threads, 2 pts x 8 cols
// per thread (16 scalar accs, ~45 regs -> 5 blocks/SM, 40 warps).
// A: [pt][k] rows, stride 66 (ty bank spread 0/4/8/12, conflict-free bcast).
// B: interleaved [k][j][cx][4]: col c at word k*64 + ((c>>2)&1)*32
//    + (c>>3)*4 + (c&3); thread cx load j = cols cx*8+4j..+3 -> acc col = cx*8+c.
// ---------------------------------------------------------------------------
#define BP     64
#define SA_LD  66
#define SA_WORDS (BP * SA_LD)              // 4224
#define SW_WORDS (64 * 64)                 // 4096
#define SMEM_BYTES ((SA_WORDS + SW_WORDS) * 4)   // 33280

__global__ __launch_bounds__(256, 5)
void k_pf2(const float* __restrict__ W2, float* __restrict__ out) {
    extern __shared__ float smem[];
    float* sA = smem;                      // [64 pt][SA_LD]
    float* sW = smem + SA_WORDS;           // interleaved B chunk

    int tid = threadIdx.x;
    int p0  = blockIdx.x * BP;             // 6250 * 64 = 400000 exactly
    int ty  = tid >> 3;                    // 0..31 -> points ty*2, ty*2+1
    int cx  = tid & 7;                     // 0..7  -> cols cx*8 .. +7

    float acc[2][8];
    #pragma unroll
    for (int p = 0; p < 2; p++)
        #pragma unroll
        for (int c = 0; c < 8; c++) acc[p][c] = 0.f;

    #pragma unroll 1
    for (int chunk = 0; chunk < 2; chunk++) {
        if (chunk) __syncthreads();

        // ---- stage B chunk interleaved
        for (int i = tid; i < 4096; i += 256) {
            int k = i >> 6, c = i & 63;
            float wv = W2[(chunk * 64 + k) * 64 + c];
            int off = k * 64 + (((c >> 2) & 1) << 5) + ((c >> 3) << 2) + (c & 3);
            sW[off] = wv;
        }

        // ---- stage A rows [pt][k]: 1024 float4 (16 threads per point row)
        for (int i = tid; i < 1024; i += 256) {
            int pt = i >> 4, q = i & 15;
            const float4* src;
            if (chunk == 0) {
                src = (const float4*)(g_pf1 + (size_t)(p0 + pt) * 64);
            } else {
                src = (const float4*)(g_v1 + (size_t)g_flat[p0 + pt] * 64);
            }
            float4 v = src[q];
            float* d = sA + pt * SA_LD + q * 4;   // 8B-aligned (66 even)
            *(float2*)(d + 0) = make_float2(v.x, v.y);
            *(float2*)(d + 2) = make_float2(v.z, v.w);
        }
        __syncthreads();

        // ---- mainloop: 64 k-steps
        const float* a0p = sA + (ty * 2 + 0) * SA_LD;
        const float* a1p = sA + (ty * 2 + 1) * SA_LD;
        #pragma unroll 8
        for (int k = 0; k < 64; k++) {
            float a0 = a0p[k];
            float a1 = a1p[k];
            const float* b = sW + k * 64 + cx * 4;
            float4 B0 = *(const float4*)(b + 0);    // cols cx*8+0..3
            float4 B1 = *(const float4*)(b + 32);   // cols cx*8+4..7
            acc[0][0] = fmaf(a0, B0.x, acc[0][0]);
            acc[0][1] = fmaf(a0, B0.y, acc[0][1]);
            acc[0][2] = fmaf(a0, B0.z, acc[0][2]);
            acc[0][3] = fmaf(a0, B0.w, acc[0][3]);
            acc[0][4] = fmaf(a0, B1.x, acc[0][4]);
            acc[0][5] = fmaf(a0, B1.y, acc[0][5]);
            acc[0][6] = fmaf(a0, B1.z, acc[0][6]);
            acc[0][7] = fmaf(a0, B1.w, acc[0][7]);
            acc[1][0] = fmaf(a1, B0.x, acc[1][0]);
            acc[1][1] = fmaf(a1, B0.y, acc[1][1]);
            acc[1][2] = fmaf(a1, B0.z, acc[1][2]);
            acc[1][3] = fmaf(a1, B0.w, acc[1][3]);
            acc[1][4] = fmaf(a1, B1.x, acc[1][4]);
            acc[1][5] = fmaf(a1, B1.y, acc[1][5]);
            acc[1][6] = fmaf(a1, B1.z, acc[1][6]);
            acc[1][7] = fmaf(a1, B1.w, acc[1][7]);
        }
    }

    // ---- epilogue: relu + guarded scatter atomicMax (out pre-zeroed)
    #pragma unroll
    for (int p = 0; p < 2; p++) {
        int gp = p0 + ty * 2 + p;
        int fl = g_flat[gp];
        int* o = (int*)(out + (size_t)fl * 64 + cx * 8);
        #pragma unroll
        for (int c = 0; c < 8; c++) {
            float v = acc[p][c];
            if (v > 0.f) atomicMax(o + c, __float_as_int(v));
        }
    }
}

// ---------------------------------------------------------------------------
extern "C" void kernel_launch(void* const* d_in, const int* in_sizes, int n_in,
                              void* d_out, int out_size) {
    const float* points = (const float*)d_in[0];  // [400000, 5]
    const float* W1     = (const float*)d_in[1];  // [11, 64]
    const float* W2     = (const float*)d_in[2];  // [128, 64]
    float* out = (float*)d_out;                   // [219024, 64]

    cudaFuncSetAttribute(k_pf2, cudaFuncAttributeMaxDynamicSharedMemorySize,
                         SMEM_BYTES);

    k_init<<<8192, 256>>>(out);
    k_scatter<<<(N_PTS + 255) / 256, 256>>>(points);
    k_pf1<<<N_PTS / 8, 256>>>(points, W1);
    k_pf2<<<N_PTS / BP, 256, SMEM_BYTES>>>(W2, out);
}